// round 1
// baseline (speedup 1.0000x reference)
#include <cuda_runtime.h>
#include <stdint.h>

// Problem constants (fixed by the dataset): D = 384 -> 96 float4 "quads" per row,
// split at quad 64 (= column 256). Node/graph counts read from in_sizes at runtime.
#define MAX_B      64
#define MAX_NODES  262144   // actual TOTAL_NODES = 160000

__device__ int g_offsets[MAX_B];
__device__ int g_cnt_in[MAX_NODES];
__device__ int g_cnt_out[MAX_NODES];

// ---------------------------------------------------------------------------
// 1) per-graph node offsets: exclusive prefix sum of org_graph_size (B is tiny)
// ---------------------------------------------------------------------------
__global__ void k_meta(const int* __restrict__ org_size, int B) {
    if (threadIdx.x == 0 && blockIdx.x == 0) {
        int acc = 0;
        for (int g = 0; g < B; ++g) {
            g_offsets[g] = acc;
            acc += org_size[g];
        }
    }
}

// ---------------------------------------------------------------------------
// 2) zero output accumulator (d_out is poisoned) + zero degree counters
// ---------------------------------------------------------------------------
__global__ void k_zero(float4* __restrict__ out4, int n4, int nodes) {
    int i = blockIdx.x * blockDim.x + threadIdx.x;
    if (i < n4) out4[i] = make_float4(0.f, 0.f, 0.f, 0.f);
    if (i < nodes) { g_cnt_in[i] = 0; g_cnt_out[i] = 0; }
}

// ---------------------------------------------------------------------------
// vector reduction: 4 floats per atomic message, no return value (REDG path)
// ---------------------------------------------------------------------------
__device__ __forceinline__ void red_add_v4(float* addr, float4 v) {
    asm volatile("red.global.add.v4.f32 [%0], {%1, %2, %3, %4};"
                 :: "l"(addr), "f"(v.x), "f"(v.y), "f"(v.z), "f"(v.w)
                 : "memory");
}

// ---------------------------------------------------------------------------
// 3) scatter: one warp per edge. Each x element is consumed exactly once:
//      cols [0,256)   -> incoming sum at node idx[e,1]
//      cols [256,384) -> outgoing sum at node idx[e,0]
//    Lane 0 bumps both degree counters.
// ---------------------------------------------------------------------------
__global__ void k_scatter(const float4* __restrict__ x,
                          const int* __restrict__ ptr,
                          const int2* __restrict__ lg,
                          float* __restrict__ out,
                          int E, int B) {
    int warp = (int)((blockIdx.x * blockDim.x + threadIdx.x) >> 5);
    int lane = threadIdx.x & 31;
    if (warp >= E) return;
    const int e = warp;

    // graph id: largest g with ptr[g] <= e (ptr is tiny & monotone; L1-broadcast)
    int g = 0;
    while (g + 1 < B && ptr[g + 1] <= e) ++g;
    const int off = g_offsets[g];

    const int2 p = lg[e];              // same address across warp -> broadcast
    const int n0 = p.x + off;          // outgoing target
    const int n1 = p.y + off;          // incoming target

    if (lane == 0) {
        atomicAdd(&g_cnt_out[n0], 1);
        atomicAdd(&g_cnt_in[n1], 1);
    }

    const float4* xr = x + (size_t)e * 96;
    // independent loads first (MLP), then fire the reductions
    float4 v0 = xr[lane];              // quads  0..31  -> cols   0..127 (incoming)
    float4 v1 = xr[lane + 32];         // quads 32..63  -> cols 128..255 (incoming)
    float4 v2 = xr[lane + 64];         // quads 64..95  -> cols 256..383 (outgoing)

    float* b1 = out + (size_t)n1 * 384;
    float* b0 = out + (size_t)n0 * 384;
    red_add_v4(b1 + (size_t)lane * 4,        v0);
    red_add_v4(b1 + (size_t)(lane + 32) * 4, v1);
    red_add_v4(b0 + (size_t)(lane + 64) * 4, v2);
}

// ---------------------------------------------------------------------------
// 4) divide sums by clamped counts (in place on d_out)
// ---------------------------------------------------------------------------
__global__ void k_div(float4* __restrict__ out4, int total4) {
    int i = blockIdx.x * blockDim.x + threadIdx.x;
    if (i >= total4) return;
    unsigned int node = (unsigned int)i / 96u;
    unsigned int q    = (unsigned int)i % 96u;
    int c = (q < 64u) ? g_cnt_in[node] : g_cnt_out[node];
    float inv = 1.0f / fmaxf((float)c, 1.0f);
    float4 v = out4[i];
    v.x *= inv; v.y *= inv; v.z *= inv; v.w *= inv;
    out4[i] = v;
}

// ---------------------------------------------------------------------------
// launch: 4 kernels on the default stream (stream order = dependency order;
// fully graph-capturable, no allocations, no syncs)
// ---------------------------------------------------------------------------
extern "C" void kernel_launch(void* const* d_in, const int* in_sizes, int n_in,
                              void* d_out, int out_size) {
    const float* x   = (const float*)d_in[0];   // [E, 384] f32
    const int*   org = (const int*)  d_in[1];   // [B]      i32
    const int*   ptr = (const int*)  d_in[2];   // [B+1]    i32
    const int*   lg  = (const int*)  d_in[3];   // [E, 2]   i32

    const int B  = in_sizes[1];
    const int E  = in_sizes[3] / 2;
    const int D  = 384;
    const int nodes = out_size / D;             // 160000
    const int n4    = out_size / 4;             // float4 count of output

    k_meta<<<1, 32>>>(org, B);

    int tz = (n4 > nodes) ? n4 : nodes;
    k_zero<<<(tz + 255) / 256, 256>>>((float4*)d_out, n4, nodes);

    long long scatter_threads = (long long)E * 32;
    k_scatter<<<(int)((scatter_threads + 255) / 256), 256>>>(
        (const float4*)x, ptr, (const int2*)lg, (float*)d_out, E, B);

    k_div<<<(n4 + 255) / 256, 256>>>((float4*)d_out, n4);
}

// round 2
// speedup vs baseline: 1.6845x; 1.6845x over previous
#include <cuda_runtime.h>
#include <stdint.h>

// ---------------------------------------------------------------------------
// Static scratch (no runtime allocation allowed). Actual sizes: B=16,
// TOTAL_NODES=160000, E=320000. Bounds chosen with headroom.
// ---------------------------------------------------------------------------
#define MAX_B        64
#define MAX_NODES    262144            // >= 160000
#define MAX_E        1048576           // >= 320000
#define SLOTS        (2 * MAX_NODES)   // concatenated: [0,nodes)=in, [nodes,2n)=out
#define SCAN_CHUNK   2048
#define SCAN_THREADS 256
#define SCAN_ITEMS   8                 // 256*8 = 2048
#define MAX_BLK      ((SLOTS + SCAN_CHUNK - 1) / SCAN_CHUNK)

__device__ int  g_offsets[MAX_B];      // per-graph node offset
__device__ int2 g_eidx[MAX_E];         // per-edge (global n0=outgoing, n1=incoming)
__device__ int  g_cnt[SLOTS];          // degree counts (in ‖ out)
__device__ int  g_start[SLOTS];        // CSR starts (exclusive scan of g_cnt)
__device__ int  g_cur[SLOTS];          // atomic fill cursors (copy of g_start)
__device__ int  g_list[2 * MAX_E];     // edge ids: incoming lists then outgoing lists
__device__ int  g_bsum[MAX_BLK];       // scan block partials
__device__ int  g_boff[MAX_BLK];       // scan block offsets

// ---------------------------------------------------------------------------
// 1) per-graph node offsets (B tiny)
// ---------------------------------------------------------------------------
__global__ void k_meta(const int* __restrict__ org_size, int B) {
    if (threadIdx.x == 0) {
        int acc = 0;
        for (int g = 0; g < B; ++g) { g_offsets[g] = acc; acc += org_size[g]; }
    }
}

// ---------------------------------------------------------------------------
// 2) zero counts
// ---------------------------------------------------------------------------
__global__ void k_zero_cnt(int slots) {
    int i = blockIdx.x * blockDim.x + threadIdx.x;
    if (i < slots) g_cnt[i] = 0;
}

// ---------------------------------------------------------------------------
// 3) per-edge: resolve global node ids, bump degree counts
// ---------------------------------------------------------------------------
__global__ void k_count(const int* __restrict__ ptr, const int2* __restrict__ lg,
                        int E, int B, int nodes) {
    int e = blockIdx.x * blockDim.x + threadIdx.x;
    if (e >= E) return;
    int g = 0;
    while (g + 1 < B && ptr[g + 1] <= e) ++g;     // ptr tiny & monotone (cached)
    const int off = g_offsets[g];
    int2 p = lg[e];
    int n0 = p.x + off;                            // outgoing target
    int n1 = p.y + off;                            // incoming target
    g_eidx[e] = make_int2(n0, n1);
    atomicAdd(&g_cnt[n1], 1);                      // in slot
    atomicAdd(&g_cnt[nodes + n0], 1);              // out slot
}

// ---------------------------------------------------------------------------
// 4) exclusive scan of g_cnt over `total` slots (3 small kernels)
// ---------------------------------------------------------------------------
__global__ void k_scan1(int total) {               // per-block partial sums
    int b = blockIdx.x, t = threadIdx.x;
    int base = b * SCAN_CHUNK + t * SCAN_ITEMS;
    int s = 0;
    #pragma unroll
    for (int i = 0; i < SCAN_ITEMS; ++i) {
        int idx = base + i;
        if (idx < total) s += g_cnt[idx];
    }
    __shared__ int sh[SCAN_THREADS];
    sh[t] = s; __syncthreads();
    for (int off = SCAN_THREADS >> 1; off > 0; off >>= 1) {
        if (t < off) sh[t] += sh[t + off];
        __syncthreads();
    }
    if (t == 0) g_bsum[b] = sh[0];
}

__global__ void k_scan2(int nblk) {                // scan the (<=256) partials
    __shared__ int sh[MAX_BLK];
    int t = threadIdx.x;
    if (t < nblk) sh[t] = g_bsum[t];
    __syncthreads();
    if (t == 0) {
        int acc = 0;
        for (int b = 0; b < nblk; ++b) { int v = sh[b]; sh[b] = acc; acc += v; }
    }
    __syncthreads();
    if (t < nblk) g_boff[t] = sh[t];
}

__global__ void k_scan3(int total) {               // final starts + cursors
    int b = blockIdx.x, t = threadIdx.x;
    int base = b * SCAN_CHUNK + t * SCAN_ITEMS;
    int v[SCAN_ITEMS]; int s = 0;
    #pragma unroll
    for (int i = 0; i < SCAN_ITEMS; ++i) {
        int idx = base + i;
        v[i] = (idx < total) ? g_cnt[idx] : 0;
        s += v[i];
    }
    __shared__ int sh[SCAN_THREADS];
    sh[t] = s; __syncthreads();
    for (int off = 1; off < SCAN_THREADS; off <<= 1) {  // Hillis-Steele inclusive
        int add = (t >= off) ? sh[t - off] : 0;
        __syncthreads();
        sh[t] += add;
        __syncthreads();
    }
    int run = g_boff[b] + sh[t] - s;               // exclusive prefix for this thread
    #pragma unroll
    for (int i = 0; i < SCAN_ITEMS; ++i) {
        int idx = base + i;
        if (idx < total) { g_start[idx] = run; g_cur[idx] = run; run += v[i]; }
    }
}

// ---------------------------------------------------------------------------
// 5) fill CSR edge lists via atomic cursors (order within a node irrelevant)
// ---------------------------------------------------------------------------
__global__ void k_fill(int E, int nodes) {
    int e = blockIdx.x * blockDim.x + threadIdx.x;
    if (e >= E) return;
    int2 p = g_eidx[e];                            // (n0=out, n1=in)
    int pi = atomicAdd(&g_cur[p.y], 1);
    g_list[pi] = e;
    int po = atomicAdd(&g_cur[nodes + p.x], 1);
    g_list[po] = e;
}

// ---------------------------------------------------------------------------
// 6) gather: one warp per node. Sums incoming edges' cols [0,256) and
//    outgoing edges' cols [256,384), divides by clamped counts, writes output
//    exactly once. No atomics, no zero pass, no divide pass.
// ---------------------------------------------------------------------------
__global__ void k_gather(const float4* __restrict__ x,
                         float4* __restrict__ out,
                         int nodes) {
    int warp = (int)((blockIdx.x * blockDim.x + threadIdx.x) >> 5);
    int lane = threadIdx.x & 31;
    if (warp >= nodes) return;
    const int n = warp;

    float4 a0 = make_float4(0.f, 0.f, 0.f, 0.f);   // quads lane      (cols 0..127)
    float4 a1 = make_float4(0.f, 0.f, 0.f, 0.f);   // quads lane+32   (cols 128..255)
    float4 a2 = make_float4(0.f, 0.f, 0.f, 0.f);   // quads lane+64   (cols 256..383)

    const int sIn  = g_start[n];
    const int cIn  = g_cnt[n];
    const int sOut = g_start[nodes + n];
    const int cOut = g_cnt[nodes + n];

    // incoming: 1KB contiguous per edge, fully coalesced across the warp
    for (int i = 0; i < cIn; ++i) {
        int e = g_list[sIn + i];                   // broadcast load
        const float4* xr = x + (size_t)e * 96;
        float4 v0 = xr[lane];
        float4 v1 = xr[lane + 32];
        a0.x += v0.x; a0.y += v0.y; a0.z += v0.z; a0.w += v0.w;
        a1.x += v1.x; a1.y += v1.y; a1.z += v1.z; a1.w += v1.w;
    }
    // outgoing: 512B contiguous per edge
    for (int i = 0; i < cOut; ++i) {
        int e = g_list[sOut + i];
        float4 v2 = x[(size_t)e * 96 + lane + 64];
        a2.x += v2.x; a2.y += v2.y; a2.z += v2.z; a2.w += v2.w;
    }

    const float invIn  = 1.0f / fmaxf((float)cIn,  1.0f);
    const float invOut = 1.0f / fmaxf((float)cOut, 1.0f);

    float4* orow = out + (size_t)n * 96;
    orow[lane]      = make_float4(a0.x * invIn,  a0.y * invIn,  a0.z * invIn,  a0.w * invIn);
    orow[lane + 32] = make_float4(a1.x * invIn,  a1.y * invIn,  a1.z * invIn,  a1.w * invIn);
    orow[lane + 64] = make_float4(a2.x * invOut, a2.y * invOut, a2.z * invOut, a2.w * invOut);
}

// ---------------------------------------------------------------------------
// launch (default stream => stream order = dependency order; graph-capturable)
// ---------------------------------------------------------------------------
extern "C" void kernel_launch(void* const* d_in, const int* in_sizes, int n_in,
                              void* d_out, int out_size) {
    const float* x   = (const float*)d_in[0];   // [E, 384] f32
    const int*   org = (const int*)  d_in[1];   // [B]      i32
    const int*   ptr = (const int*)  d_in[2];   // [B+1]    i32
    const int*   lg  = (const int*)  d_in[3];   // [E, 2]   i32

    const int B     = in_sizes[1];
    const int E     = in_sizes[3] / 2;
    const int nodes = out_size / 384;           // 160000
    const int slots = 2 * nodes;

    k_meta<<<1, 32>>>(org, B);
    k_zero_cnt<<<(slots + 255) / 256, 256>>>(slots);
    k_count<<<(E + 255) / 256, 256>>>(ptr, (const int2*)lg, E, B, nodes);

    const int nblk = (slots + SCAN_CHUNK - 1) / SCAN_CHUNK;
    k_scan1<<<nblk, SCAN_THREADS>>>(slots);
    k_scan2<<<1, SCAN_THREADS>>>(nblk);
    k_scan3<<<nblk, SCAN_THREADS>>>(slots);

    k_fill<<<(E + 255) / 256, 256>>>(E, nodes);

    long long gthreads = (long long)nodes * 32;
    k_gather<<<(int)((gthreads + 255) / 256), 256>>>(
        (const float4*)x, (float4*)d_out, nodes);
}